// round 2
// baseline (speedup 1.0000x reference)
#include <cuda_runtime.h>
#include <cstddef>

#define NODE_DIM 128
#define EDGE_DIM 128
#define N_A 512
#define N_B 512
#define M_EDGES (N_A * N_B)

// Scratch (static device allocations are the sanctioned alloc-free path)
__device__ float g_h[(size_t)M_EDGES * EDGE_DIM];   // 134 MB intermediate h
__device__ float g_aproj[N_A * EDGE_DIM];           // nodes_a @ Wa + be1
__device__ float g_bproj[N_B * EDGE_DIM];           // nodes_b @ Wb
__device__ float g_suma[N_A * EDGE_DIM];
__device__ float g_sumb[N_B * EDGE_DIM];

// ---------------------------------------------------------------------------
// K1: per-node projections. blocks [0,512) -> aproj (+be1), [512,1024) -> bproj
// ---------------------------------------------------------------------------
__global__ void proj_kernel(const float* __restrict__ na, const float* __restrict__ nb,
                            const float* __restrict__ We1, const float* __restrict__ be1) {
    __shared__ float x[NODE_DIM];
    int i = blockIdx.x, d = threadIdx.x;
    const float* src;
    float* dst;
    const float* W;
    float acc;
    if (i < N_A) {
        src = na + i * NODE_DIM;
        dst = g_aproj + i * EDGE_DIM;
        W = We1;                       // Wa = We1 rows [0,128)
        acc = be1[d];                  // fold be1 into aproj
    } else {
        src = nb + (i - N_A) * NODE_DIM;
        dst = g_bproj + (i - N_A) * EDGE_DIM;
        W = We1 + NODE_DIM * EDGE_DIM; // Wb = We1 rows [128,256)
        acc = 0.f;
    }
    x[d] = src[d];
    __syncthreads();
#pragma unroll 8
    for (int k = 0; k < NODE_DIM; k++) acc = fmaf(x[k], W[k * EDGE_DIM + d], acc);
    dst[d] = acc;
}

// ---------------------------------------------------------------------------
// Tiled fp32 GEMM, BM=128, BN=128 (full N), BK=16, 256 threads, 8x8/thread.
// MODE 1: C = relu(A@B + aproj[a] + bproj[b])   (A=edge_embeds, C=g_h)
// MODE 2: C = relu(g_h@B + bias)                (C=d_out edge_latent)
// ---------------------------------------------------------------------------
template <int KDIM, int LDA, int MODE>
__global__ void __launch_bounds__(256) gemm_kernel(const float* __restrict__ A_in,
                                                   const float* __restrict__ B,
                                                   const float* __restrict__ bias,
                                                   float* __restrict__ C_out) {
    __shared__ float As[16][128];
    __shared__ float Bs[16][128];
    __shared__ float ap[128];

    const int tid = threadIdx.x;
    const int m0 = blockIdx.x * 128;
    const int tx = tid & 15;
    const int ty = tid >> 4;

    const float* A = (MODE == 2) ? (const float*)g_h : A_in;
    float* C = (MODE == 1) ? g_h : C_out;

    if (tid < 128) {
        if (MODE == 1)
            ap[tid] = g_aproj[(m0 >> 9) * EDGE_DIM + tid];  // a is constant per block
        else
            ap[tid] = bias[tid];
    }

    float acc[8][8];
#pragma unroll
    for (int i = 0; i < 8; i++)
#pragma unroll
        for (int j = 0; j < 8; j++) acc[i][j] = 0.f;

    for (int kt = 0; kt < KDIM; kt += 16) {
        // A tile: 128 rows x 16 k, coalesced float4 global loads, transposed store
#pragma unroll
        for (int l = 0; l < 2; l++) {
            int idx = tid + l * 256;
            int row = idx >> 2;
            int c4 = (idx & 3) * 4;
            float4 v = *(const float4*)(A + (size_t)(m0 + row) * LDA + kt + c4);
            As[c4 + 0][row] = v.x;
            As[c4 + 1][row] = v.y;
            As[c4 + 2][row] = v.z;
            As[c4 + 3][row] = v.w;
        }
        // B tile: 16 k-rows x 128 n
#pragma unroll
        for (int l = 0; l < 2; l++) {
            int idx = tid + l * 256;
            int kr = idx >> 5;
            int c = (idx & 31) * 4;
            *(float4*)&Bs[kr][c] = *(const float4*)(B + (size_t)(kt + kr) * 128 + c);
        }
        __syncthreads();

#pragma unroll
        for (int kk = 0; kk < 16; kk++) {
            float ra[8], rb[8];
            *(float4*)&ra[0] = *(float4*)&As[kk][ty * 8];
            *(float4*)&ra[4] = *(float4*)&As[kk][ty * 8 + 4];
            *(float4*)&rb[0] = *(float4*)&Bs[kk][tx * 8];
            *(float4*)&rb[4] = *(float4*)&Bs[kk][tx * 8 + 4];
#pragma unroll
            for (int i = 0; i < 8; i++)
#pragma unroll
                for (int j = 0; j < 8; j++) acc[i][j] = fmaf(ra[i], rb[j], acc[i][j]);
        }
        __syncthreads();
    }

    // Epilogue
    const int b0 = m0 & (N_B - 1);
#pragma unroll
    for (int i = 0; i < 8; i++) {
        int r = ty * 8 + i;
        int m = m0 + r;
        const float* bp = g_bproj + (b0 + r) * EDGE_DIM;  // only used in MODE 1
#pragma unroll
        for (int j = 0; j < 8; j += 4) {
            int n = tx * 8 + j;
            float4 v;
            v.x = acc[i][j + 0] + ap[n + 0];
            v.y = acc[i][j + 1] + ap[n + 1];
            v.z = acc[i][j + 2] + ap[n + 2];
            v.w = acc[i][j + 3] + ap[n + 3];
            if (MODE == 1) {
                v.x += bp[n + 0];
                v.y += bp[n + 1];
                v.z += bp[n + 2];
                v.w += bp[n + 3];
            }
            v.x = fmaxf(v.x, 0.f);
            v.y = fmaxf(v.y, 0.f);
            v.z = fmaxf(v.z, 0.f);
            v.w = fmaxf(v.w, 0.f);
            *(float4*)(C + (size_t)m * 128 + n) = v;
        }
    }
}

// ---------------------------------------------------------------------------
// K4: row/col sums of edge_latent. blocks [0,512): sum over b -> g_suma[a]
//                                  blocks [512,1024): sum over a -> g_sumb[b]
// ---------------------------------------------------------------------------
__global__ void sum_kernel(const float* __restrict__ lat) {
    int i = blockIdx.x, d = threadIdx.x;  // 128 threads, one per feature dim
    float a0 = 0.f, a1 = 0.f, a2 = 0.f, a3 = 0.f;
    if (i < N_A) {
        const float* p = lat + (size_t)i * N_B * EDGE_DIM + d;
#pragma unroll 4
        for (int b = 0; b < N_B; b += 4) {
            a0 += p[(size_t)(b + 0) * EDGE_DIM];
            a1 += p[(size_t)(b + 1) * EDGE_DIM];
            a2 += p[(size_t)(b + 2) * EDGE_DIM];
            a3 += p[(size_t)(b + 3) * EDGE_DIM];
        }
        g_suma[i * EDGE_DIM + d] = (a0 + a1) + (a2 + a3);
    } else {
        int b = i - N_A;
        const float* p = lat + (size_t)b * EDGE_DIM + d;
#pragma unroll 4
        for (int a = 0; a < N_A; a += 4) {
            a0 += p[(size_t)(a + 0) * N_B * EDGE_DIM];
            a1 += p[(size_t)(a + 1) * N_B * EDGE_DIM];
            a2 += p[(size_t)(a + 2) * N_B * EDGE_DIM];
            a3 += p[(size_t)(a + 3) * N_B * EDGE_DIM];
        }
        g_sumb[b * EDGE_DIM + d] = (a0 + a1) + (a2 + a3);
    }
}

// ---------------------------------------------------------------------------
// K5: node MLPs. blocks [0,512): nodes_a row; [512,1024): nodes_b row.
// out layout: [nodes_a (512x128) | nodes_b (512x128)] appended after edge_latent
// ---------------------------------------------------------------------------
__global__ void node_mlp_kernel(const float* __restrict__ na, const float* __restrict__ nb,
                                const float* __restrict__ Wn1, const float* __restrict__ bn1,
                                const float* __restrict__ Wn2, const float* __restrict__ bn2,
                                float* __restrict__ out_nodes) {
    __shared__ float x[2 * NODE_DIM];
    __shared__ float hsm[NODE_DIM];
    int i = blockIdx.x, d = threadIdx.x;
    const float* emb;
    const float* sum;
    float* o;
    if (i < N_A) {
        emb = na + i * NODE_DIM;
        sum = g_suma + i * EDGE_DIM;
        o = out_nodes + (size_t)i * NODE_DIM;
    } else {
        emb = nb + (i - N_A) * NODE_DIM;
        sum = g_sumb + (i - N_A) * EDGE_DIM;
        o = out_nodes + (size_t)N_A * NODE_DIM + (size_t)(i - N_A) * NODE_DIM;
    }
    x[d] = emb[d];
    x[NODE_DIM + d] = sum[d];
    __syncthreads();
    float acc = bn1[d];
#pragma unroll 8
    for (int k = 0; k < 2 * NODE_DIM; k++) acc = fmaf(x[k], Wn1[k * NODE_DIM + d], acc);
    hsm[d] = fmaxf(acc, 0.f);
    __syncthreads();
    acc = bn2[d];
#pragma unroll 8
    for (int k = 0; k < NODE_DIM; k++) acc = fmaf(hsm[k], Wn2[k * NODE_DIM + d], acc);
    o[d] = fmaxf(acc, 0.f);
}

// ---------------------------------------------------------------------------
extern "C" void kernel_launch(void* const* d_in, const int* in_sizes, int n_in,
                              void* d_out, int out_size) {
    const float* edge = (const float*)d_in[0];
    const float* na   = (const float*)d_in[1];
    const float* nb   = (const float*)d_in[2];
    const float* We1  = (const float*)d_in[3];
    const float* be1  = (const float*)d_in[4];
    const float* We2  = (const float*)d_in[5];
    const float* be2  = (const float*)d_in[6];
    const float* Wn1  = (const float*)d_in[7];
    const float* bn1  = (const float*)d_in[8];
    const float* Wn2  = (const float*)d_in[9];
    const float* bn2  = (const float*)d_in[10];
    float* out = (float*)d_out;

    const float* We_edge = We1 + 2 * NODE_DIM * EDGE_DIM;  // We = We1 rows [256,512)

    // K1: projections (+be1 folded into aproj)
    proj_kernel<<<N_A + N_B, 128>>>(na, nb, We1, be1);

    // K2: h = relu(edge @ We + aproj[a] + bproj[b])  -> g_h
    gemm_kernel<256, 256, 1><<<M_EDGES / 128, 256>>>(edge, We_edge, nullptr, nullptr);

    // K3: edge_latent = relu(h @ We2 + be2) -> d_out[0 : M*128)
    gemm_kernel<128, 128, 2><<<M_EDGES / 128, 256>>>(nullptr, We2, be2, out);

    // K4: sums over rows/cols of edge_latent
    sum_kernel<<<N_A + N_B, 128>>>(out);

    // K5: node MLPs -> d_out tail
    node_mlp_kernel<<<N_A + N_B, 128>>>(na, nb, Wn1, bn1, Wn2, bn2,
                                        out + (size_t)M_EDGES * EDGE_DIM);
}

// round 4
// speedup vs baseline: 1.9435x; 1.9435x over previous
#include <cuda_runtime.h>
#include <cuda_bf16.h>
#include <cstdint>
#include <cstddef>

#define NODE_DIM 128
#define EDGE_DIM 128
#define N_A 512
#define N_B 512
#define M_EDGES (N_A * N_B)

// ---------------------------------------------------------------------------
// Device scratch
// ---------------------------------------------------------------------------
__device__ float g_aproj[N_A * EDGE_DIM];   // nodes_a @ Wa + be1
__device__ float g_bproj[N_B * EDGE_DIM];   // nodes_b @ Wb
__device__ float g_suma[N_A * EDGE_DIM];
__device__ float g_sumb[N_B * EDGE_DIM];
// Pre-split, pre-transposed weight images (bf16), layout [chunk][split][n(128)][k(64)]
__device__ __nv_bfloat16 g_Bimg1[4 * 2 * 128 * 64];  // We  (256x128): 4 K-chunks
__device__ __nv_bfloat16 g_Bimg2[2 * 2 * 128 * 64];  // We2 (128x128): 2 K-chunks

// ---------------------------------------------------------------------------
// PTX helpers (compute_80+ features only — no 'a'-gated instructions)
// ---------------------------------------------------------------------------
__device__ __forceinline__ uint32_t smem_u32(const void* p) {
    uint32_t a;
    asm("{ .reg .u64 t; cvta.to.shared.u64 t, %1; cvt.u32.u64 %0, t; }" : "=r"(a) : "l"(p));
    return a;
}
__device__ __forceinline__ void ldsm_x4(uint32_t addr, uint32_t* r) {
    asm volatile("ldmatrix.sync.aligned.m8n8.x4.shared.b16 {%0,%1,%2,%3}, [%4];"
                 : "=r"(r[0]), "=r"(r[1]), "=r"(r[2]), "=r"(r[3]) : "r"(addr));
}
__device__ __forceinline__ void mma_bf16(float* c, const uint32_t* a, uint32_t b0, uint32_t b1) {
    asm volatile(
        "mma.sync.aligned.m16n8k16.row.col.f32.bf16.bf16.f32 "
        "{%0,%1,%2,%3}, {%4,%5,%6,%7}, {%8,%9}, {%0,%1,%2,%3};"
        : "+f"(c[0]), "+f"(c[1]), "+f"(c[2]), "+f"(c[3])
        : "r"(a[0]), "r"(a[1]), "r"(a[2]), "r"(a[3]), "r"(b0), "r"(b1));
}

// SMEM layout (bytes). Padded row stride: 72 bf16 = 144 B (ldmatrix conflict-free).
#define RSTRIDE 144
#define BLK 18432                 /* one [128][72] bf16 image          */
#define AS_OFF 0                  /* A chunk: hi,lo  (2*BLK)           */
#define BS_OFF (2 * BLK)          /* B chunk: hi,lo  (2*BLK)           */
#define HS_OFF (4 * BLK)          /* h: [chunk][split] (4*BLK)         */
#define WS2_OFF (8 * BLK)         /* We2: [chunk][split] (4*BLK)       */
#define SMEM_BYTES (12 * BLK)     /* 221184 */

// ---------------------------------------------------------------------------
// prep: build [chunk][split][n][64] bf16 hi/lo weight images. B[n][k]=W[k][n].
// ---------------------------------------------------------------------------
__global__ void prep_kernel(const float* __restrict__ We1, const float* __restrict__ We2) {
    int tid = threadIdx.x;
    if (blockIdx.x < 128) {
        int eid = blockIdx.x * 256 + tid;   // [0, 32768)
        int kc = eid >> 13;                 // 4 chunks of 8192
        int n = (eid >> 6) & 127;
        int kk = eid & 63;
        float wv = We1[(2 * NODE_DIM + kc * 64 + kk) * EDGE_DIM + n];
        __nv_bfloat16 hi = __float2bfloat16_rn(wv);
        __nv_bfloat16 lo = __float2bfloat16_rn(wv - __bfloat162float(hi));
        size_t base = (size_t)(kc * 2) * 8192 + n * 64 + kk;
        g_Bimg1[base] = hi;
        g_Bimg1[base + 8192] = lo;
    } else {
        int eid = (blockIdx.x - 128) * 256 + tid;  // [0, 16384)
        int kc = eid >> 13;
        int n = (eid >> 6) & 127;
        int kk = eid & 63;
        float wv = We2[(kc * 64 + kk) * EDGE_DIM + n];
        __nv_bfloat16 hi = __float2bfloat16_rn(wv);
        __nv_bfloat16 lo = __float2bfloat16_rn(wv - __bfloat162float(hi));
        size_t base = (size_t)(kc * 2) * 8192 + n * 64 + kk;
        g_Bimg2[base] = hi;
        g_Bimg2[base + 8192] = lo;
    }
}

// ---------------------------------------------------------------------------
// K1: per-node projections (exact fp32)
// ---------------------------------------------------------------------------
__global__ void proj_kernel(const float* __restrict__ na, const float* __restrict__ nb,
                            const float* __restrict__ We1, const float* __restrict__ be1) {
    __shared__ float x[NODE_DIM];
    int i = blockIdx.x, d = threadIdx.x;
    const float* src;
    float* dst;
    const float* W;
    float acc;
    if (i < N_A) {
        src = na + i * NODE_DIM;
        dst = g_aproj + i * EDGE_DIM;
        W = We1;
        acc = be1[d];
    } else {
        src = nb + (i - N_A) * NODE_DIM;
        dst = g_bproj + (i - N_A) * EDGE_DIM;
        W = We1 + NODE_DIM * EDGE_DIM;
        acc = 0.f;
    }
    x[d] = src[d];
    __syncthreads();
#pragma unroll 8
    for (int k = 0; k < NODE_DIM; k++) acc = fmaf(x[k], W[k * EDGE_DIM + d], acc);
    dst[d] = acc;
}

// ---------------------------------------------------------------------------
// Fused edge pipeline: GEMM1(+bias+ReLU) -> GEMM2(+bias+ReLU)
// mma.sync bf16, 3-way split precision. One 128x128 edge tile per CTA.
// 8 warps in 4x2 grid: warp tile 32 rows x 64 cols.
// ---------------------------------------------------------------------------
__global__ void __launch_bounds__(256, 1) fused_kernel(const float* __restrict__ edge,
                                                       const float* __restrict__ be2,
                                                       float* __restrict__ out) {
    extern __shared__ __align__(128) char smem_c[];
    const uint32_t sb = smem_u32(smem_c);
    const int tid = threadIdx.x;
    const int wid = tid >> 5;
    const int lane = tid & 31;
    const int wm = wid >> 1;        // 0..3 (row blocks of 32)
    const int wn = wid & 1;         // 0..1 (col halves of 64)
    const int m0 = blockIdx.x * 128;
    const int a_idx = m0 >> 9;
    const int b0 = m0 & (N_B - 1);

    // Per-lane ldmatrix offsets (bytes, within an image)
    // A-frag (m16k16): lanes 0-15 -> rows 0-15 (k+0), lanes 16-31 -> rows 0-15 (k+8)
    const uint32_t a_loff = (uint32_t)(wm * 32 + (lane & 15)) * RSTRIDE + ((lane >> 4) << 4);
    // B-frag pair (two n8 tiles): n = (lane&7) + (lane>>4)*8 ; k += ((lane>>3)&1)*8
    const uint32_t b_loff = (uint32_t)(wn * 64 + (lane & 7) + ((lane >> 4) << 3)) * RSTRIDE +
                            (((lane >> 3) & 1) << 4);

    // ---- Preload We2 image into SMEM (resident for GEMM2) ----
    {
        const uint2* src = (const uint2*)g_Bimg2;
#pragma unroll
        for (int i = 0; i < 32; i++) {
            int idx = tid + i * 256;            // [0, 8192)
            int sc = idx >> 11;                 // [chunk*2+split]
            int rem = idx & 2047;
            int n = rem >> 4;
            int p = rem & 15;
            *(uint2*)(smem_c + WS2_OFF + sc * BLK + n * RSTRIDE + p * 8) = src[idx];
        }
    }

    float acc[2][8][4];
#pragma unroll
    for (int mt = 0; mt < 2; mt++)
#pragma unroll
        for (int nt = 0; nt < 8; nt++)
#pragma unroll
            for (int q = 0; q < 4; q++) acc[mt][nt][q] = 0.f;

    // ================= GEMM1: edge_tile @ We (K=256, 4 chunks) ==============
    for (int kc = 0; kc < 4; kc++) {
        __syncthreads();
        // load + split A chunk [128 rows x 64 k] fp32 -> bf16 hi/lo
        {
            const float* Ag = edge + (size_t)m0 * 256 + kc * 64;
#pragma unroll
            for (int i = 0; i < 8; i++) {
                int idx = tid + i * 256;
                int row = idx >> 4;
                int f4 = idx & 15;
                float4 v = *(const float4*)(Ag + (size_t)row * 256 + f4 * 4);
                __nv_bfloat162 h01 = __floats2bfloat162_rn(v.x, v.y);
                __nv_bfloat162 h23 = __floats2bfloat162_rn(v.z, v.w);
                uint32_t u01 = *reinterpret_cast<uint32_t*>(&h01);
                uint32_t u23 = *reinterpret_cast<uint32_t*>(&h23);
                float l0 = v.x - __uint_as_float(u01 << 16);
                float l1 = v.y - __uint_as_float(u01 & 0xffff0000u);
                float l2 = v.z - __uint_as_float(u23 << 16);
                float l3 = v.w - __uint_as_float(u23 & 0xffff0000u);
                __nv_bfloat162 lo01 = __floats2bfloat162_rn(l0, l1);
                __nv_bfloat162 lo23 = __floats2bfloat162_rn(l2, l3);
                uint32_t boff = (uint32_t)row * RSTRIDE + f4 * 8;
                *(uint2*)(smem_c + AS_OFF + boff) = make_uint2(u01, u23);
                *(uint2*)(smem_c + AS_OFF + BLK + boff) =
                    make_uint2(*reinterpret_cast<uint32_t*>(&lo01),
                               *reinterpret_cast<uint32_t*>(&lo23));
            }
        }
        // copy B chunk image (hi+lo) with padding
        {
            const uint2* src = (const uint2*)(g_Bimg1 + (size_t)kc * 16384);
#pragma unroll
            for (int i = 0; i < 16; i++) {
                int idx = tid + i * 256;   // [0, 4096)
                int split = idx >> 11;
                int rem = idx & 2047;
                int n = rem >> 4;
                int p = rem & 15;
                *(uint2*)(smem_c + BS_OFF + split * BLK + n * RSTRIDE + p * 8) = src[idx];
            }
        }
        __syncthreads();

#pragma unroll
        for (int ks = 0; ks < 4; ks++) {
            const uint32_t kb = ks << 5;  // k0*2 bytes
#pragma unroll
            for (int s = 0; s < 3; s++) {
                const uint32_t aB = sb + AS_OFF + ((s == 2) ? BLK : 0) + a_loff + kb;
                const uint32_t bB = sb + BS_OFF + ((s == 1) ? BLK : 0) + b_loff + kb;
                uint32_t af[2][4];
                ldsm_x4(aB, af[0]);
                ldsm_x4(aB + 16 * RSTRIDE, af[1]);
#pragma unroll
                for (int np = 0; np < 4; np++) {
                    uint32_t bf[4];
                    ldsm_x4(bB + np * 16 * RSTRIDE, bf);
#pragma unroll
                    for (int mt = 0; mt < 2; mt++) {
                        mma_bf16(acc[mt][2 * np], af[mt], bf[0], bf[1]);
                        mma_bf16(acc[mt][2 * np + 1], af[mt], bf[2], bf[3]);
                    }
                }
            }
        }
    }
    __syncthreads();

    // ---- Epilogue 1: h = relu(D + aproj + bproj), split to bf16 hi/lo in SMEM
    {
        const int qrow = lane >> 2;
        const int qcol = (lane & 3) * 2;
#pragma unroll
        for (int mt = 0; mt < 2; mt++) {
            int r_base = wm * 32 + mt * 16 + qrow;
#pragma unroll
            for (int nt = 0; nt < 8; nt++) {
                int col = wn * 64 + nt * 8 + qcol;
                float2 ap = __ldg((const float2*)(g_aproj + a_idx * 128 + col));
#pragma unroll
                for (int hf = 0; hf < 2; hf++) {
                    int row = r_base + 8 * hf;
                    float2 bp = __ldg((const float2*)(g_bproj + (size_t)(b0 + row) * 128 + col));
                    float v0 = fmaxf(acc[mt][nt][2 * hf] + ap.x + bp.x, 0.f);
                    float v1 = fmaxf(acc[mt][nt][2 * hf + 1] + ap.y + bp.y, 0.f);
                    __nv_bfloat162 h01 = __floats2bfloat162_rn(v0, v1);
                    uint32_t u01 = *reinterpret_cast<uint32_t*>(&h01);
                    float l0 = v0 - __uint_as_float(u01 << 16);
                    float l1 = v1 - __uint_as_float(u01 & 0xffff0000u);
                    __nv_bfloat162 lo01 = __floats2bfloat162_rn(l0, l1);
                    int ch = col >> 6;
                    uint32_t boff = (uint32_t)row * RSTRIDE + (col & 63) * 2;
                    *(uint32_t*)(smem_c + HS_OFF + ch * 2 * BLK + boff) = u01;
                    *(uint32_t*)(smem_c + HS_OFF + (ch * 2 + 1) * BLK + boff) =
                        *reinterpret_cast<uint32_t*>(&lo01);
                    // reset acc for GEMM2
                    acc[mt][nt][2 * hf] = 0.f;
                    acc[mt][nt][2 * hf + 1] = 0.f;
                }
            }
        }
    }
    __syncthreads();

    // ================= GEMM2: h @ We2 (K=128, 2 chunks) =====================
#pragma unroll
    for (int ch = 0; ch < 2; ch++) {
#pragma unroll
        for (int ks = 0; ks < 4; ks++) {
            const uint32_t kb = ks << 5;
#pragma unroll
            for (int s = 0; s < 3; s++) {
                const uint32_t aB = sb + HS_OFF + ch * 2 * BLK + ((s == 2) ? BLK : 0) + a_loff + kb;
                const uint32_t bB = sb + WS2_OFF + ch * 2 * BLK + ((s == 1) ? BLK : 0) + b_loff + kb;
                uint32_t af[2][4];
                ldsm_x4(aB, af[0]);
                ldsm_x4(aB + 16 * RSTRIDE, af[1]);
#pragma unroll
                for (int np = 0; np < 4; np++) {
                    uint32_t bf[4];
                    ldsm_x4(bB + np * 16 * RSTRIDE, bf);
#pragma unroll
                    for (int mt = 0; mt < 2; mt++) {
                        mma_bf16(acc[mt][2 * np], af[mt], bf[0], bf[1]);
                        mma_bf16(acc[mt][2 * np + 1], af[mt], bf[2], bf[3]);
                    }
                }
            }
        }
    }

    // ---- Epilogue 2: out = relu(D + be2) ----
    {
        const int qrow = lane >> 2;
        const int qcol = (lane & 3) * 2;
#pragma unroll
        for (int mt = 0; mt < 2; mt++) {
            int r_base = wm * 32 + mt * 16 + qrow;
#pragma unroll
            for (int nt = 0; nt < 8; nt++) {
                int col = wn * 64 + nt * 8 + qcol;
                float2 bz = __ldg((const float2*)(be2 + col));
#pragma unroll
                for (int hf = 0; hf < 2; hf++) {
                    int row = r_base + 8 * hf;
                    float2 w;
                    w.x = fmaxf(acc[mt][nt][2 * hf] + bz.x, 0.f);
                    w.y = fmaxf(acc[mt][nt][2 * hf + 1] + bz.y, 0.f);
                    *(float2*)(out + (size_t)(m0 + row) * 128 + col) = w;
                }
            }
        }
    }
}

// ---------------------------------------------------------------------------
// K4: row/col sums (float4 + 8-way ILP)
// ---------------------------------------------------------------------------
__global__ void __launch_bounds__(256) sum_kernel(const float* __restrict__ lat) {
    __shared__ float4 red[8][33];
    int i = blockIdx.x;
    int d4 = threadIdx.x & 31;
    int g = threadIdx.x >> 5;
    float x = 0.f, y = 0.f, z = 0.f, w = 0.f;
    if (i < N_A) {
        const float4* p = (const float4*)lat + (size_t)i * (N_B * 32);
        for (int b = g; b < N_B; b += 8) {
            float4 v = p[b * 32 + d4];
            x += v.x; y += v.y; z += v.z; w += v.w;
        }
    } else {
        const float4* p = (const float4*)lat + (size_t)(i - N_A) * 32;
        for (int a2 = g; a2 < N_A; a2 += 8) {
            float4 v = p[(size_t)a2 * (N_B * 32) + d4];
            x += v.x; y += v.y; z += v.z; w += v.w;
        }
    }
    red[g][d4] = make_float4(x, y, z, w);
    __syncthreads();
    if (g == 0) {
#pragma unroll
        for (int k = 1; k < 8; k++) {
            float4 v = red[k][d4];
            x += v.x; y += v.y; z += v.z; w += v.w;
        }
        float* dst = (i < N_A) ? (g_suma + i * EDGE_DIM) : (g_sumb + (i - N_A) * EDGE_DIM);
        ((float4*)dst)[d4] = make_float4(x, y, z, w);
    }
}

// ---------------------------------------------------------------------------
// K5: node MLPs
// ---------------------------------------------------------------------------
__global__ void node_mlp_kernel(const float* __restrict__ na, const float* __restrict__ nb,
                                const float* __restrict__ Wn1, const float* __restrict__ bn1,
                                const float* __restrict__ Wn2, const float* __restrict__ bn2,
                                float* __restrict__ out_nodes) {
    __shared__ float x[2 * NODE_DIM];
    __shared__ float hsm[NODE_DIM];
    int i = blockIdx.x, d = threadIdx.x;
    const float* emb;
    const float* sum;
    float* o;
    if (i < N_A) {
        emb = na + i * NODE_DIM;
        sum = g_suma + i * EDGE_DIM;
        o = out_nodes + (size_t)i * NODE_DIM;
    } else {
        emb = nb + (i - N_A) * NODE_DIM;
        sum = g_sumb + (i - N_A) * EDGE_DIM;
        o = out_nodes + (size_t)N_A * NODE_DIM + (size_t)(i - N_A) * NODE_DIM;
    }
    x[d] = emb[d];
    x[NODE_DIM + d] = sum[d];
    __syncthreads();
    float acc = bn1[d];
#pragma unroll 8
    for (int k = 0; k < 2 * NODE_DIM; k++) acc = fmaf(x[k], Wn1[k * NODE_DIM + d], acc);
    hsm[d] = fmaxf(acc, 0.f);
    __syncthreads();
    acc = bn2[d];
#pragma unroll 8
    for (int k = 0; k < NODE_DIM; k++) acc = fmaf(hsm[k], Wn2[k * NODE_DIM + d], acc);
    o[d] = fmaxf(acc, 0.f);
}

// ---------------------------------------------------------------------------
extern "C" void kernel_launch(void* const* d_in, const int* in_sizes, int n_in,
                              void* d_out, int out_size) {
    const float* edge = (const float*)d_in[0];
    const float* na   = (const float*)d_in[1];
    const float* nb   = (const float*)d_in[2];
    const float* We1  = (const float*)d_in[3];
    const float* be1  = (const float*)d_in[4];
    const float* We2  = (const float*)d_in[5];
    const float* be2  = (const float*)d_in[6];
    const float* Wn1  = (const float*)d_in[7];
    const float* bn1  = (const float*)d_in[8];
    const float* Wn2  = (const float*)d_in[9];
    const float* bn2  = (const float*)d_in[10];
    float* out = (float*)d_out;

    static int smem_set = 0;
    if (!smem_set) {
        cudaFuncSetAttribute(fused_kernel, cudaFuncAttributeMaxDynamicSharedMemorySize,
                             SMEM_BYTES);
        smem_set = 1;
    }

    prep_kernel<<<192, 256>>>(We1, We2);
    proj_kernel<<<N_A + N_B, 128>>>(na, nb, We1, be1);
    fused_kernel<<<M_EDGES / 128, 256, SMEM_BYTES>>>(edge, be2, out);
    sum_kernel<<<N_A + N_B, 256>>>(out);
    node_mlp_kernel<<<N_A + N_B, 128>>>(na, nb, Wn1, bn1, Wn2, bn2,
                                        out + (size_t)M_EDGES * EDGE_DIM);
}

// round 5
// speedup vs baseline: 2.5823x; 1.3287x over previous
#include <cuda_runtime.h>
#include <cuda_fp16.h>
#include <cstdint>
#include <cstddef>

#define NODE_DIM 128
#define EDGE_DIM 128
#define N_A 512
#define N_B 512
#define M_EDGES (N_A * N_B)

// ---------------------------------------------------------------------------
// Device scratch
// ---------------------------------------------------------------------------
__device__ float g_aproj[N_A * EDGE_DIM];   // nodes_a @ Wa + be1
__device__ float g_bproj[N_B * EDGE_DIM];   // nodes_b @ Wb
__device__ float g_suma[N_A * EDGE_DIM];
__device__ float g_sumb[N_B * EDGE_DIM];
// Pre-split (hi/lo fp16), pre-transposed weight images: [chunk][split][n(128)][k(64)]
__device__ __half g_Bimg1[4 * 2 * 8192];  // We  (256x128): 4 K-chunks
__device__ __half g_Bimg2[2 * 2 * 8192];  // We2 (128x128): 2 K-chunks

// ---------------------------------------------------------------------------
// PTX helpers (compute_80+ only)
// ---------------------------------------------------------------------------
__device__ __forceinline__ uint32_t smem_u32(const void* p) {
    uint32_t a;
    asm("{ .reg .u64 t; cvta.to.shared.u64 t, %1; cvt.u32.u64 %0, t; }" : "=r"(a) : "l"(p));
    return a;
}
__device__ __forceinline__ void ldsm_x4(uint32_t addr, uint32_t* r) {
    asm volatile("ldmatrix.sync.aligned.m8n8.x4.shared.b16 {%0,%1,%2,%3}, [%4];"
                 : "=r"(r[0]), "=r"(r[1]), "=r"(r[2]), "=r"(r[3]) : "r"(addr));
}
__device__ __forceinline__ void mma_f16(float* c, const uint32_t* a, uint32_t b0, uint32_t b1) {
    asm volatile(
        "mma.sync.aligned.m16n8k16.row.col.f32.f16.f16.f32 "
        "{%0,%1,%2,%3}, {%4,%5,%6,%7}, {%8,%9}, {%0,%1,%2,%3};"
        : "+f"(c[0]), "+f"(c[1]), "+f"(c[2]), "+f"(c[3])
        : "r"(a[0]), "r"(a[1]), "r"(a[2]), "r"(a[3]), "r"(b0), "r"(b1));
}
#define CP_ASYNC16(dst, src) \
    asm volatile("cp.async.cg.shared.global [%0], [%1], 16;" :: "r"(dst), "l"(src))
#define CP_COMMIT() asm volatile("cp.async.commit_group;" ::: "memory")
#define CP_WAIT_ALL() asm volatile("cp.async.wait_group 0;" ::: "memory")

// SMEM layout. Padded row stride: 72 fp16 = 144 B (conflict-free ldmatrix).
#define RSTRIDE 144
#define BLK 18432                   /* one [128][72] b16 image */
#define AS_OFF 0                    /* A: 2 bufs (single split)       -> 2 BLK */
#define BS_OFF (2 * BLK)            /* B: 2 bufs x hi/lo              -> 4 BLK */
#define HS_OFF (6 * BLK)            /* h: 2 chunks (single split)     -> 2 BLK */
#define WS2_OFF (8 * BLK)           /* We2: 2 chunks x hi/lo          -> 4 BLK */
#define SMEM_BYTES (12 * BLK)       /* 221184 */

// ---------------------------------------------------------------------------
// prep: fp16 hi/lo split of transposed weights. B[n][k] = W[k][n].
// ---------------------------------------------------------------------------
__global__ void prep_kernel(const float* __restrict__ We1, const float* __restrict__ We2) {
    int tid = threadIdx.x;
    if (blockIdx.x < 128) {
        int eid = blockIdx.x * 256 + tid;   // [0, 32768)
        int kc = eid >> 13;
        int n = (eid >> 6) & 127;
        int kk = eid & 63;
        float wv = We1[(2 * NODE_DIM + kc * 64 + kk) * EDGE_DIM + n];
        __half hi = __float2half_rn(wv);
        __half lo = __float2half_rn(wv - __half2float(hi));
        size_t base = (size_t)(kc * 2) * 8192 + n * 64 + kk;
        g_Bimg1[base] = hi;
        g_Bimg1[base + 8192] = lo;
    } else {
        int eid = (blockIdx.x - 128) * 256 + tid;  // [0, 16384)
        int kc = eid >> 13;
        int n = (eid >> 6) & 127;
        int kk = eid & 63;
        float wv = We2[(kc * 64 + kk) * EDGE_DIM + n];
        __half hi = __float2half_rn(wv);
        __half lo = __float2half_rn(wv - __half2float(hi));
        size_t base = (size_t)(kc * 2) * 8192 + n * 64 + kk;
        g_Bimg2[base] = hi;
        g_Bimg2[base + 8192] = lo;
    }
}

// ---------------------------------------------------------------------------
// K1: per-node projections (exact fp32)
// ---------------------------------------------------------------------------
__global__ void proj_kernel(const float* __restrict__ na, const float* __restrict__ nb,
                            const float* __restrict__ We1, const float* __restrict__ be1) {
    __shared__ float x[NODE_DIM];
    int i = blockIdx.x, d = threadIdx.x;
    const float* src;
    float* dst;
    const float* W;
    float acc;
    if (i < N_A) {
        src = na + i * NODE_DIM;
        dst = g_aproj + i * EDGE_DIM;
        W = We1;
        acc = be1[d];
    } else {
        src = nb + (i - N_A) * NODE_DIM;
        dst = g_bproj + (i - N_A) * EDGE_DIM;
        W = We1 + NODE_DIM * EDGE_DIM;
        acc = 0.f;
    }
    x[d] = src[d];
    __syncthreads();
#pragma unroll 8
    for (int k = 0; k < NODE_DIM; k++) acc = fmaf(x[k], W[k * EDGE_DIM + d], acc);
    dst[d] = acc;
}

// ---------------------------------------------------------------------------
// Fused edge pipeline, fp16 2-pass split precision, pipelined mainloop.
// 8 warps (4x2): warp tile 32 x 64. One 128x128 edge tile per CTA.
// ---------------------------------------------------------------------------
__global__ void __launch_bounds__(256, 1) fused_kernel(const float* __restrict__ edge,
                                                       const float* __restrict__ be2,
                                                       float* __restrict__ out) {
    extern __shared__ __align__(128) char smem_c[];
    const uint32_t sb = smem_u32(smem_c);
    const int tid = threadIdx.x;
    const int wid = tid >> 5;
    const int lane = tid & 31;
    const int wm = wid >> 1;
    const int wn = wid & 1;
    const int m0 = blockIdx.x * 128;
    const int a_idx = m0 >> 9;
    const int b0 = m0 & (N_B - 1);

    // ldmatrix per-lane offsets (within one [128][72] image)
    const uint32_t a_loff = (uint32_t)(wm * 32 + (lane & 15)) * RSTRIDE + ((lane >> 4) << 4);
    const uint32_t b_loff = (uint32_t)(wn * 64 + (lane & 7) + ((lane >> 4) << 3)) * RSTRIDE +
                            (((lane >> 3) & 1) << 4);

    // ---- Prologue: We2 images + B chunk 0 via cp.async; A chunk 0 via LDG ----
    {
        const char* src = (const char*)g_Bimg2;
#pragma unroll
        for (int i = 0; i < 16; i++) {
            int idx = tid + i * 256;            // [0, 4096) 16B units
            int sc = idx >> 10;                 // ch*2+split
            int rem = idx & 1023;
            int n = rem >> 3;
            int p = rem & 7;
            CP_ASYNC16(sb + WS2_OFF + sc * BLK + n * RSTRIDE + p * 16, src + (size_t)idx * 16);
        }
        CP_COMMIT();
    }
    {
        const char* src = (const char*)g_Bimg1;  // chunk 0
#pragma unroll
        for (int i = 0; i < 8; i++) {
            int idx = tid + i * 256;            // [0, 2048)
            int s = idx >> 10;
            int rem = idx & 1023;
            int n = rem >> 3;
            int p = rem & 7;
            CP_ASYNC16(sb + BS_OFF + s * BLK + n * RSTRIDE + p * 16, src + (size_t)idx * 16);
        }
        CP_COMMIT();
    }
    float4 regsA[8];
    {
        const float* Ag = edge + (size_t)m0 * 256;
#pragma unroll
        for (int i = 0; i < 8; i++) {
            int idx = tid + i * 256;
            int row = idx >> 4;
            int f4 = idx & 15;
            regsA[i] = *(const float4*)(Ag + (size_t)row * 256 + f4 * 4);
        }
    }

    float acc[2][8][4];
#pragma unroll
    for (int mt = 0; mt < 2; mt++)
#pragma unroll
        for (int nt = 0; nt < 8; nt++)
#pragma unroll
            for (int q = 0; q < 4; q++) acc[mt][nt][q] = 0.f;

    // ================= GEMM1: edge_tile @ We (K=256, 4 chunks) ==============
    for (int kc = 0; kc < 4; kc++) {
        const int buf = kc & 1;
        // convert + store A chunk kc (fp32 -> fp16 single image)
#pragma unroll
        for (int i = 0; i < 8; i++) {
            int idx = tid + i * 256;
            int row = idx >> 4;
            int f4 = idx & 15;
            float4 v = regsA[i];
            __half2 h01 = __floats2half2_rn(v.x, v.y);
            __half2 h23 = __floats2half2_rn(v.z, v.w);
            *(uint2*)(smem_c + AS_OFF + buf * BLK + (uint32_t)row * RSTRIDE + f4 * 8) =
                make_uint2(*reinterpret_cast<uint32_t*>(&h01),
                           *reinterpret_cast<uint32_t*>(&h23));
        }
        CP_WAIT_ALL();     // B chunk kc (and We2 on kc==0) landed
        __syncthreads();
        // issue prefetches for chunk kc+1 (overlap with MMA below)
        if (kc < 3) {
            const char* srcB = (const char*)(g_Bimg1 + (size_t)(kc + 1) * 16384);
#pragma unroll
            for (int i = 0; i < 8; i++) {
                int idx = tid + i * 256;
                int s = idx >> 10;
                int rem = idx & 1023;
                int n = rem >> 3;
                int p = rem & 7;
                CP_ASYNC16(sb + BS_OFF + ((buf ^ 1) * 2 + s) * BLK + n * RSTRIDE + p * 16,
                           srcB + (size_t)idx * 16);
            }
            CP_COMMIT();
            const float* Ag = edge + (size_t)m0 * 256 + (kc + 1) * 64;
#pragma unroll
            for (int i = 0; i < 8; i++) {
                int idx = tid + i * 256;
                int row = idx >> 4;
                int f4 = idx & 15;
                regsA[i] = *(const float4*)(Ag + (size_t)row * 256 + f4 * 4);
            }
        }
        // MMA over chunk kc
#pragma unroll
        for (int ks = 0; ks < 4; ks++) {
            const uint32_t kb = ks << 5;
            const uint32_t aB = sb + AS_OFF + buf * BLK + a_loff + kb;
            uint32_t af[2][4];
            ldsm_x4(aB, af[0]);
            ldsm_x4(aB + 16 * RSTRIDE, af[1]);
#pragma unroll
            for (int s = 0; s < 2; s++) {
                const uint32_t bB = sb + BS_OFF + (buf * 2 + s) * BLK + b_loff + kb;
#pragma unroll
                for (int np = 0; np < 4; np++) {
                    uint32_t bf[4];
                    ldsm_x4(bB + np * 16 * RSTRIDE, bf);
#pragma unroll
                    for (int mt = 0; mt < 2; mt++) {
                        mma_f16(acc[mt][2 * np], af[mt], bf[0], bf[1]);
                        mma_f16(acc[mt][2 * np + 1], af[mt], bf[2], bf[3]);
                    }
                }
            }
        }
    }

    // ---- Epilogue 1: h = relu(D + aproj + bproj) -> fp16 image in SMEM ----
    {
        const int qrow = lane >> 2;
        const int qcol = (lane & 3) * 2;
#pragma unroll
        for (int mt = 0; mt < 2; mt++) {
            int r_base = wm * 32 + mt * 16 + qrow;
#pragma unroll
            for (int nt = 0; nt < 8; nt++) {
                int col = wn * 64 + nt * 8 + qcol;
                float2 ap = __ldg((const float2*)(g_aproj + a_idx * 128 + col));
#pragma unroll
                for (int hf = 0; hf < 2; hf++) {
                    int row = r_base + 8 * hf;
                    float2 bp = __ldg((const float2*)(g_bproj + (size_t)(b0 + row) * 128 + col));
                    float v0 = fmaxf(acc[mt][nt][2 * hf] + ap.x + bp.x, 0.f);
                    float v1 = fmaxf(acc[mt][nt][2 * hf + 1] + ap.y + bp.y, 0.f);
                    __half2 h01 = __floats2half2_rn(v0, v1);
                    int ch = col >> 6;
                    *(uint32_t*)(smem_c + HS_OFF + ch * BLK + (uint32_t)row * RSTRIDE +
                                 (col & 63) * 2) = *reinterpret_cast<uint32_t*>(&h01);
                    acc[mt][nt][2 * hf] = 0.f;
                    acc[mt][nt][2 * hf + 1] = 0.f;
                }
            }
        }
    }
    __syncthreads();

    // ================= GEMM2: h @ We2 (K=128, 2 chunks) =====================
#pragma unroll
    for (int ch = 0; ch < 2; ch++) {
#pragma unroll
        for (int ks = 0; ks < 4; ks++) {
            const uint32_t kb = ks << 5;
            const uint32_t aB = sb + HS_OFF + ch * BLK + a_loff + kb;
            uint32_t af[2][4];
            ldsm_x4(aB, af[0]);
            ldsm_x4(aB + 16 * RSTRIDE, af[1]);
#pragma unroll
            for (int s = 0; s < 2; s++) {
                const uint32_t bB = sb + WS2_OFF + (ch * 2 + s) * BLK + b_loff + kb;
#pragma unroll
                for (int np = 0; np < 4; np++) {
                    uint32_t bf[4];
                    ldsm_x4(bB + np * 16 * RSTRIDE, bf);
#pragma unroll
                    for (int mt = 0; mt < 2; mt++) {
                        mma_f16(acc[mt][2 * np], af[mt], bf[0], bf[1]);
                        mma_f16(acc[mt][2 * np + 1], af[mt], bf[2], bf[3]);
                    }
                }
            }
        }
    }

    // ---- Epilogue 2: out = relu(D + be2) ----
    {
        const int qrow = lane >> 2;
        const int qcol = (lane & 3) * 2;
#pragma unroll
        for (int mt = 0; mt < 2; mt++) {
            int r_base = wm * 32 + mt * 16 + qrow;
#pragma unroll
            for (int nt = 0; nt < 8; nt++) {
                int col = wn * 64 + nt * 8 + qcol;
                float2 bz = __ldg((const float2*)(be2 + col));
#pragma unroll
                for (int hf = 0; hf < 2; hf++) {
                    int row = r_base + 8 * hf;
                    float2 w;
                    w.x = fmaxf(acc[mt][nt][2 * hf] + bz.x, 0.f);
                    w.y = fmaxf(acc[mt][nt][2 * hf + 1] + bz.y, 0.f);
                    *(float2*)(out + (size_t)(m0 + row) * 128 + col) = w;
                }
            }
        }
    }
}

// ---------------------------------------------------------------------------
// K4: row/col sums
// ---------------------------------------------------------------------------
__global__ void __launch_bounds__(256) sum_kernel(const float* __restrict__ lat) {
    __shared__ float4 red[8][33];
    int i = blockIdx.x;
    int d4 = threadIdx.x & 31;
    int g = threadIdx.x >> 5;
    float x = 0.f, y = 0.f, z = 0.f, w = 0.f;
    if (i < N_A) {
        const float4* p = (const float4*)lat + (size_t)i * (N_B * 32);
        for (int b = g; b < N_B; b += 8) {
            float4 v = p[b * 32 + d4];
            x += v.x; y += v.y; z += v.z; w += v.w;
        }
    } else {
        const float4* p = (const float4*)lat + (size_t)(i - N_A) * 32;
        for (int a2 = g; a2 < N_A; a2 += 8) {
            float4 v = p[(size_t)a2 * (N_B * 32) + d4];
            x += v.x; y += v.y; z += v.z; w += v.w;
        }
    }
    red[g][d4] = make_float4(x, y, z, w);
    __syncthreads();
    if (g == 0) {
#pragma unroll
        for (int k = 1; k < 8; k++) {
            float4 v = red[k][d4];
            x += v.x; y += v.y; z += v.z; w += v.w;
        }
        float* dst = (i < N_A) ? (g_suma + i * EDGE_DIM) : (g_sumb + (i - N_A) * EDGE_DIM);
        ((float4*)dst)[d4] = make_float4(x, y, z, w);
    }
}

// ---------------------------------------------------------------------------
// K5: node MLPs
// ---------------------------------------------------------------------------
__global__ void node_mlp_kernel(const float* __restrict__ na, const float* __restrict__ nb,
                                const float* __restrict__ Wn1, const float* __restrict__ bn1,
                                const float* __restrict__ Wn2, const float* __restrict__ bn2,
                                float* __restrict__ out_nodes) {
    __shared__ float x[2 * NODE_DIM];
    __shared__ float hsm[NODE_DIM];
    int i = blockIdx.x, d = threadIdx.x;
    const float* emb;
    const float* sum;
    float* o;
    if (i < N_A) {
        emb = na + i * NODE_DIM;
        sum = g_suma + i * EDGE_DIM;
        o = out_nodes + (size_t)i * NODE_DIM;
    } else {
        emb = nb + (i - N_A) * NODE_DIM;
        sum = g_sumb + (i - N_A) * EDGE_DIM;
        o = out_nodes + (size_t)N_A * NODE_DIM + (size_t)(i - N_A) * NODE_DIM;
    }
    x[d] = emb[d];
    x[NODE_DIM + d] = sum[d];
    __syncthreads();
    float acc = bn1[d];
#pragma unroll 8
    for (int k = 0; k < 2 * NODE_DIM; k++) acc = fmaf(x[k], Wn1[k * NODE_DIM + d], acc);
    hsm[d] = fmaxf(acc, 0.f);
    __syncthreads();
    acc = bn2[d];
#pragma unroll 8
    for (int k = 0; k < NODE_DIM; k++) acc = fmaf(hsm[k], Wn2[k * NODE_DIM + d], acc);
    o[d] = fmaxf(acc, 0.f);
}

// ---------------------------------------------------------------------------
extern "C" void kernel_launch(void* const* d_in, const int* in_sizes, int n_in,
                              void* d_out, int out_size) {
    const float* edge = (const float*)d_in[0];
    const float* na   = (const float*)d_in[1];
    const float* nb   = (const float*)d_in[2];
    const float* We1  = (const float*)d_in[3];
    const float* be1  = (const float*)d_in[4];
    const float* We2  = (const float*)d_in[5];
    const float* be2  = (const float*)d_in[6];
    const float* Wn1  = (const float*)d_in[7];
    const float* bn1  = (const float*)d_in[8];
    const float* Wn2  = (const float*)d_in[9];
    const float* bn2  = (const float*)d_in[10];
    float* out = (float*)d_out;

    static int smem_set = 0;
    if (!smem_set) {
        cudaFuncSetAttribute(fused_kernel, cudaFuncAttributeMaxDynamicSharedMemorySize,
                             SMEM_BYTES);
        smem_set = 1;
    }

    prep_kernel<<<192, 256>>>(We1, We2);
    proj_kernel<<<N_A + N_B, 128>>>(na, nb, We1, be1);
    fused_kernel<<<M_EDGES / 128, 256, SMEM_BYTES>>>(edge, be2, out);
    sum_kernel<<<N_A + N_B, 256>>>(out);
    node_mlp_kernel<<<N_A + N_B, 128>>>(na, nb, Wn1, bn1, Wn2, bn2,
                                        out + (size_t)M_EDGES * EDGE_DIM);
}

// round 6
// speedup vs baseline: 3.2713x; 1.2668x over previous
#include <cuda_runtime.h>
#include <cuda_fp16.h>
#include <cstdint>
#include <cstddef>

#define NODE_DIM 128
#define EDGE_DIM 128
#define N_A 512
#define N_B 512
#define M_EDGES (N_A * N_B)

// ---------------------------------------------------------------------------
// Device scratch
// ---------------------------------------------------------------------------
__device__ float g_aproj[N_A * EDGE_DIM];   // nodes_a @ Wa + be1
__device__ float g_bproj[N_B * EDGE_DIM];   // nodes_b @ Wb
__device__ float g_suma[N_A * EDGE_DIM];
__device__ float g_sumb[N_B * EDGE_DIM];
// Pre-transposed fp16 weight images: [chunk][n(128)][k(64)]
__device__ __half g_Bimg1[4 * 8192];  // We  (256x128): 4 K-chunks
__device__ __half g_Bimg2[2 * 8192];  // We2 (128x128): 2 K-chunks

// ---------------------------------------------------------------------------
// PTX helpers (compute_80+ only)
// ---------------------------------------------------------------------------
__device__ __forceinline__ uint32_t smem_u32(const void* p) {
    uint32_t a;
    asm("{ .reg .u64 t; cvta.to.shared.u64 t, %1; cvt.u32.u64 %0, t; }" : "=r"(a) : "l"(p));
    return a;
}
__device__ __forceinline__ void ldsm_x4(uint32_t addr, uint32_t* r) {
    asm volatile("ldmatrix.sync.aligned.m8n8.x4.shared.b16 {%0,%1,%2,%3}, [%4];"
                 : "=r"(r[0]), "=r"(r[1]), "=r"(r[2]), "=r"(r[3]) : "r"(addr));
}
__device__ __forceinline__ void mma_f16(float* c, const uint32_t* a, uint32_t b0, uint32_t b1) {
    asm volatile(
        "mma.sync.aligned.m16n8k16.row.col.f32.f16.f16.f32 "
        "{%0,%1,%2,%3}, {%4,%5,%6,%7}, {%8,%9}, {%0,%1,%2,%3};"
        : "+f"(c[0]), "+f"(c[1]), "+f"(c[2]), "+f"(c[3])
        : "r"(a[0]), "r"(a[1]), "r"(a[2]), "r"(a[3]), "r"(b0), "r"(b1));
}
#define CP_ASYNC16(dst, src) \
    asm volatile("cp.async.cg.shared.global [%0], [%1], 16;" :: "r"(dst), "l"(src))
#define CP_COMMIT() asm volatile("cp.async.commit_group;" ::: "memory")
#define CP_WAIT_ALL() asm volatile("cp.async.wait_group 0;" ::: "memory")

// SMEM layout. Padded row stride: 72 fp16 = 144 B (conflict-free ldmatrix).
#define RSTRIDE 144
#define BLK 18432                   /* one [128][72] b16 image */
#define AS_OFF 0                    /* A: 2 bufs     -> 2 BLK */
#define BS_OFF (2 * BLK)            /* B: 2 bufs     -> 2 BLK */
#define HS_OFF (4 * BLK)            /* h: 2 chunks   -> 2 BLK */
#define WS2_OFF (6 * BLK)           /* We2: 2 chunks -> 2 BLK */
#define SMEM_BYTES (8 * BLK)        /* 147456 */

// ---------------------------------------------------------------------------
// prep: fp16 transposed weight images. B[n][k] = W[k][n].
// ---------------------------------------------------------------------------
__global__ void prep_kernel(const float* __restrict__ We1, const float* __restrict__ We2) {
    int tid = threadIdx.x;
    if (blockIdx.x < 128) {
        int eid = blockIdx.x * 256 + tid;   // [0, 32768)
        int kc = eid >> 13;
        int n = (eid >> 6) & 127;
        int kk = eid & 63;
        float wv = We1[(2 * NODE_DIM + kc * 64 + kk) * EDGE_DIM + n];
        g_Bimg1[(size_t)kc * 8192 + n * 64 + kk] = __float2half_rn(wv);
    } else {
        int eid = (blockIdx.x - 128) * 256 + tid;  // [0, 16384)
        int kc = eid >> 13;
        int n = (eid >> 6) & 127;
        int kk = eid & 63;
        float wv = We2[(kc * 64 + kk) * EDGE_DIM + n];
        g_Bimg2[(size_t)kc * 8192 + n * 64 + kk] = __float2half_rn(wv);
    }
}

// ---------------------------------------------------------------------------
// K1: per-node projections (exact fp32)
// ---------------------------------------------------------------------------
__global__ void proj_kernel(const float* __restrict__ na, const float* __restrict__ nb,
                            const float* __restrict__ We1, const float* __restrict__ be1) {
    __shared__ float x[NODE_DIM];
    int i = blockIdx.x, d = threadIdx.x;
    const float* src;
    float* dst;
    const float* W;
    float acc;
    if (i < N_A) {
        src = na + i * NODE_DIM;
        dst = g_aproj + i * EDGE_DIM;
        W = We1;
        acc = be1[d];
    } else {
        src = nb + (i - N_A) * NODE_DIM;
        dst = g_bproj + (i - N_A) * EDGE_DIM;
        W = We1 + NODE_DIM * EDGE_DIM;
        acc = 0.f;
    }
    x[d] = src[d];
    __syncthreads();
#pragma unroll 8
    for (int k = 0; k < NODE_DIM; k++) acc = fmaf(x[k], W[k * EDGE_DIM + d], acc);
    dst[d] = acc;
}

// ---------------------------------------------------------------------------
// Fused edge pipeline, single-pass fp16, pipelined mainloop.
// 8 warps (4x2): warp tile 32 x 64. One 128x128 edge tile per CTA.
// ---------------------------------------------------------------------------
__global__ void __launch_bounds__(256, 1) fused_kernel(const float* __restrict__ edge,
                                                       const float* __restrict__ be2,
                                                       float* __restrict__ out) {
    extern __shared__ __align__(128) char smem_c[];
    const uint32_t sb = smem_u32(smem_c);
    const int tid = threadIdx.x;
    const int wid = tid >> 5;
    const int lane = tid & 31;
    const int wm = wid >> 1;
    const int wn = wid & 1;
    const int m0 = blockIdx.x * 128;
    const int a_idx = m0 >> 9;
    const int b0 = m0 & (N_B - 1);

    // ldmatrix per-lane offsets (within one [128][72] image)
    const uint32_t a_loff = (uint32_t)(wm * 32 + (lane & 15)) * RSTRIDE + ((lane >> 4) << 4);
    const uint32_t b_loff = (uint32_t)(wn * 64 + (lane & 7) + ((lane >> 4) << 3)) * RSTRIDE +
                            (((lane >> 3) & 1) << 4);

    // ---- Prologue: We2 images + B chunk 0 via cp.async; A chunk 0 via LDG ----
    {
        const char* src = (const char*)g_Bimg2;
#pragma unroll
        for (int i = 0; i < 8; i++) {
            int idx = tid + i * 256;            // [0, 2048) 16B units
            int ch = idx >> 10;
            int rem = idx & 1023;
            int n = rem >> 3;
            int p = rem & 7;
            CP_ASYNC16(sb + WS2_OFF + ch * BLK + n * RSTRIDE + p * 16, src + (size_t)idx * 16);
        }
        CP_COMMIT();
    }
    {
        const char* src = (const char*)g_Bimg1;  // chunk 0
#pragma unroll
        for (int i = 0; i < 4; i++) {
            int idx = tid + i * 256;            // [0, 1024)
            int n = idx >> 3;
            int p = idx & 7;
            CP_ASYNC16(sb + BS_OFF + n * RSTRIDE + p * 16, src + (size_t)idx * 16);
        }
        CP_COMMIT();
    }
    float4 regsA[8];
    {
        const float* Ag = edge + (size_t)m0 * 256;
#pragma unroll
        for (int i = 0; i < 8; i++) {
            int idx = tid + i * 256;
            int row = idx >> 4;
            int f4 = idx & 15;
            regsA[i] = *(const float4*)(Ag + (size_t)row * 256 + f4 * 4);
        }
    }

    float acc[2][8][4];
#pragma unroll
    for (int mt = 0; mt < 2; mt++)
#pragma unroll
        for (int nt = 0; nt < 8; nt++)
#pragma unroll
            for (int q = 0; q < 4; q++) acc[mt][nt][q] = 0.f;

    // ================= GEMM1: edge_tile @ We (K=256, 4 chunks) ==============
    for (int kc = 0; kc < 4; kc++) {
        const int buf = kc & 1;
        // convert + store A chunk kc (fp32 -> fp16)
#pragma unroll
        for (int i = 0; i < 8; i++) {
            int idx = tid + i * 256;
            int row = idx >> 4;
            int f4 = idx & 15;
            float4 v = regsA[i];
            __half2 h01 = __floats2half2_rn(v.x, v.y);
            __half2 h23 = __floats2half2_rn(v.z, v.w);
            *(uint2*)(smem_c + AS_OFF + buf * BLK + (uint32_t)row * RSTRIDE + f4 * 8) =
                make_uint2(*reinterpret_cast<uint32_t*>(&h01),
                           *reinterpret_cast<uint32_t*>(&h23));
        }
        CP_WAIT_ALL();     // B chunk kc (and We2 on kc==0) landed
        __syncthreads();
        // issue prefetches for chunk kc+1 (overlap with MMA below)
        if (kc < 3) {
            const char* srcB = (const char*)(g_Bimg1 + (size_t)(kc + 1) * 8192);
#pragma unroll
            for (int i = 0; i < 4; i++) {
                int idx = tid + i * 256;
                int n = idx >> 3;
                int p = idx & 7;
                CP_ASYNC16(sb + BS_OFF + (buf ^ 1) * BLK + n * RSTRIDE + p * 16,
                           srcB + (size_t)idx * 16);
            }
            CP_COMMIT();
            const float* Ag = edge + (size_t)m0 * 256 + (kc + 1) * 64;
#pragma unroll
            for (int i = 0; i < 8; i++) {
                int idx = tid + i * 256;
                int row = idx >> 4;
                int f4 = idx & 15;
                regsA[i] = *(const float4*)(Ag + (size_t)row * 256 + f4 * 4);
            }
        }
        // MMA over chunk kc
#pragma unroll
        for (int ks = 0; ks < 4; ks++) {
            const uint32_t kb = ks << 5;
            const uint32_t aB = sb + AS_OFF + buf * BLK + a_loff + kb;
            const uint32_t bB = sb + BS_OFF + buf * BLK + b_loff + kb;
            uint32_t af[2][4];
            ldsm_x4(aB, af[0]);
            ldsm_x4(aB + 16 * RSTRIDE, af[1]);
#pragma unroll
            for (int np = 0; np < 4; np++) {
                uint32_t bf[4];
                ldsm_x4(bB + np * 16 * RSTRIDE, bf);
#pragma unroll
                for (int mt = 0; mt < 2; mt++) {
                    mma_f16(acc[mt][2 * np], af[mt], bf[0], bf[1]);
                    mma_f16(acc[mt][2 * np + 1], af[mt], bf[2], bf[3]);
                }
            }
        }
    }

    // ---- Epilogue 1: h = relu(D + aproj + bproj) -> fp16 image in SMEM ----
    {
        const int qrow = lane >> 2;
        const int qcol = (lane & 3) * 2;
#pragma unroll
        for (int mt = 0; mt < 2; mt++) {
            int r_base = wm * 32 + mt * 16 + qrow;
#pragma unroll
            for (int nt = 0; nt < 8; nt++) {
                int col = wn * 64 + nt * 8 + qcol;
                float2 ap = __ldg((const float2*)(g_aproj + a_idx * 128 + col));
#pragma unroll
                for (int hf = 0; hf < 2; hf++) {
                    int row = r_base + 8 * hf;
                    float2 bp = __ldg((const float2*)(g_bproj + (size_t)(b0 + row) * 128 + col));
                    float v0 = fmaxf(acc[mt][nt][2 * hf] + ap.x + bp.x, 0.f);
                    float v1 = fmaxf(acc[mt][nt][2 * hf + 1] + ap.y + bp.y, 0.f);
                    __half2 h01 = __floats2half2_rn(v0, v1);
                    int ch = col >> 6;
                    *(uint32_t*)(smem_c + HS_OFF + ch * BLK + (uint32_t)row * RSTRIDE +
                                 (col & 63) * 2) = *reinterpret_cast<uint32_t*>(&h01);
                    acc[mt][nt][2 * hf] = 0.f;
                    acc[mt][nt][2 * hf + 1] = 0.f;
                }
            }
        }
    }
    __syncthreads();

    // ================= GEMM2: h @ We2 (K=128, 2 chunks) =====================
#pragma unroll
    for (int ch = 0; ch < 2; ch++) {
#pragma unroll
        for (int ks = 0; ks < 4; ks++) {
            const uint32_t kb = ks << 5;
            const uint32_t aB = sb + HS_OFF + ch * BLK + a_loff + kb;
            const uint32_t bB = sb + WS2_OFF + ch * BLK + b_loff + kb;
            uint32_t af[2][4];
            ldsm_x4(aB, af[0]);
            ldsm_x4(aB + 16 * RSTRIDE, af[1]);
#pragma unroll
            for (int np = 0; np < 4; np++) {
                uint32_t bf[4];
                ldsm_x4(bB + np * 16 * RSTRIDE, bf);
#pragma unroll
                for (int mt = 0; mt < 2; mt++) {
                    mma_f16(acc[mt][2 * np], af[mt], bf[0], bf[1]);
                    mma_f16(acc[mt][2 * np + 1], af[mt], bf[2], bf[3]);
                }
            }
        }
    }

    // ---- Epilogue 2: out = relu(D + be2) ----
    {
        const int qrow = lane >> 2;
        const int qcol = (lane & 3) * 2;
#pragma unroll
        for (int mt = 0; mt < 2; mt++) {
            int r_base = wm * 32 + mt * 16 + qrow;
#pragma unroll
            for (int nt = 0; nt < 8; nt++) {
                int col = wn * 64 + nt * 8 + qcol;
                float2 bz = __ldg((const float2*)(be2 + col));
#pragma unroll
                for (int hf = 0; hf < 2; hf++) {
                    int row = r_base + 8 * hf;
                    float2 w;
                    w.x = fmaxf(acc[mt][nt][2 * hf] + bz.x, 0.f);
                    w.y = fmaxf(acc[mt][nt][2 * hf + 1] + bz.y, 0.f);
                    *(float2*)(out + (size_t)(m0 + row) * 128 + col) = w;
                }
            }
        }
    }
}

// ---------------------------------------------------------------------------
// K4: row/col sums
// ---------------------------------------------------------------------------
__global__ void __launch_bounds__(256) sum_kernel(const float* __restrict__ lat) {
    __shared__ float4 red[8][33];
    int i = blockIdx.x;
    int d4 = threadIdx.x & 31;
    int g = threadIdx.x >> 5;
    float x = 0.f, y = 0.f, z = 0.f, w = 0.f;
    if (i < N_A) {
        const float4* p = (const float4*)lat + (size_t)i * (N_B * 32);
        for (int b = g; b < N_B; b += 8) {
            float4 v = p[b * 32 + d4];
            x += v.x; y += v.y; z += v.z; w += v.w;
        }
    } else {
        const float4* p = (const float4*)lat + (size_t)(i - N_A) * 32;
        for (int a2 = g; a2 < N_A; a2 += 8) {
            float4 v = p[(size_t)a2 * (N_B * 32) + d4];
            x += v.x; y += v.y; z += v.z; w += v.w;
        }
    }
    red[g][d4] = make_float4(x, y, z, w);
    __syncthreads();
    if (g == 0) {
#pragma unroll
        for (int k = 1; k < 8; k++) {
            float4 v = red[k][d4];
            x += v.x; y += v.y; z += v.z; w += v.w;
        }
        float* dst = (i < N_A) ? (g_suma + i * EDGE_DIM) : (g_sumb + (i - N_A) * EDGE_DIM);
        ((float4*)dst)[d4] = make_float4(x, y, z, w);
    }
}

// ---------------------------------------------------------------------------
// K5: node MLPs
// ---------------------------------------------------------------------------
__global__ void node_mlp_kernel(const float* __restrict__ na, const float* __restrict__ nb,
                                const float* __restrict__ Wn1, const float* __restrict__ bn1,
                                const float* __restrict__ Wn2, const float* __restrict__ bn2,
                                float* __restrict__ out_nodes) {
    __shared__ float x[2 * NODE_DIM];
    __shared__ float hsm[NODE_DIM];
    int i = blockIdx.x, d = threadIdx.x;
    const float* emb;
    const float* sum;
    float* o;
    if (i < N_A) {
        emb = na + i * NODE_DIM;
        sum = g_suma + i * EDGE_DIM;
        o = out_nodes + (size_t)i * NODE_DIM;
    } else {
        emb = nb + (i - N_A) * NODE_DIM;
        sum = g_sumb + (i - N_A) * EDGE_DIM;
        o = out_nodes + (size_t)N_A * NODE_DIM + (size_t)(i - N_A) * NODE_DIM;
    }
    x[d] = emb[d];
    x[NODE_DIM + d] = sum[d];
    __syncthreads();
    float acc = bn1[d];
#pragma unroll 8
    for (int k = 0; k < 2 * NODE_DIM; k++) acc = fmaf(x[k], Wn1[k * NODE_DIM + d], acc);
    hsm[d] = fmaxf(acc, 0.f);
    __syncthreads();
    acc = bn2[d];
#pragma unroll 8
    for (int k = 0; k < NODE_DIM; k++) acc = fmaf(hsm[k], Wn2[k * NODE_DIM + d], acc);
    o[d] = fmaxf(acc, 0.f);
}

// ---------------------------------------------------------------------------
extern "C" void kernel_launch(void* const* d_in, const int* in_sizes, int n_in,
                              void* d_out, int out_size) {
    const float* edge = (const float*)d_in[0];
    const float* na   = (const float*)d_in[1];
    const float* nb   = (const float*)d_in[2];
    const float* We1  = (const float*)d_in[3];
    const float* be1  = (const float*)d_in[4];
    const float* We2  = (const float*)d_in[5];
    const float* be2  = (const float*)d_in[6];
    const float* Wn1  = (const float*)d_in[7];
    const float* bn1  = (const float*)d_in[8];
    const float* Wn2  = (const float*)d_in[9];
    const float* bn2  = (const float*)d_in[10];
    float* out = (float*)d_out;

    static int smem_set = 0;
    if (!smem_set) {
        cudaFuncSetAttribute(fused_kernel, cudaFuncAttributeMaxDynamicSharedMemorySize,
                             SMEM_BYTES);
        smem_set = 1;
    }

    prep_kernel<<<192, 256>>>(We1, We2);
    proj_kernel<<<N_A + N_B, 128>>>(na, nb, We1, be1);
    fused_kernel<<<M_EDGES / 128, 256, SMEM_BYTES>>>(edge, be2, out);
    sum_kernel<<<N_A + N_B, 256>>>(out);
    node_mlp_kernel<<<N_A + N_B, 128>>>(na, nb, Wn1, bn1, Wn2, bn2,
                                        out + (size_t)M_EDGES * EDGE_DIM);
}

// round 7
// speedup vs baseline: 3.8461x; 1.1757x over previous
#include <cuda_runtime.h>
#include <cuda_fp16.h>
#include <cstdint>
#include <cstddef>

#define NODE_DIM 128
#define EDGE_DIM 128
#define N_A 512
#define N_B 512
#define M_EDGES (N_A * N_B)

// ---------------------------------------------------------------------------
// Device scratch
// ---------------------------------------------------------------------------
__device__ float g_aproj[N_A * EDGE_DIM];   // nodes_a @ Wa + be1
__device__ float g_bproj[N_B * EDGE_DIM];   // nodes_b @ Wb
__device__ float g_suma[N_A * EDGE_DIM];    // accumulated by fused kernel (atomics)
__device__ float g_sumb[N_B * EDGE_DIM];
// Pre-transposed fp16 weight images: [chunk][n(128)][k(64)]
__device__ __half g_Bimg1[4 * 8192];  // We  (256x128): 4 K-chunks
__device__ __half g_Bimg2[2 * 8192];  // We2 (128x128): 2 K-chunks

// ---------------------------------------------------------------------------
// PTX helpers (compute_80+ only)
// ---------------------------------------------------------------------------
__device__ __forceinline__ uint32_t smem_u32(const void* p) {
    uint32_t a;
    asm("{ .reg .u64 t; cvta.to.shared.u64 t, %1; cvt.u32.u64 %0, t; }" : "=r"(a) : "l"(p));
    return a;
}
__device__ __forceinline__ void ldsm_x4(uint32_t addr, uint32_t* r) {
    asm volatile("ldmatrix.sync.aligned.m8n8.x4.shared.b16 {%0,%1,%2,%3}, [%4];"
                 : "=r"(r[0]), "=r"(r[1]), "=r"(r[2]), "=r"(r[3]) : "r"(addr));
}
__device__ __forceinline__ void mma_f16(float* c, const uint32_t* a, uint32_t b0, uint32_t b1) {
    asm volatile(
        "mma.sync.aligned.m16n8k16.row.col.f32.f16.f16.f32 "
        "{%0,%1,%2,%3}, {%4,%5,%6,%7}, {%8,%9}, {%0,%1,%2,%3};"
        : "+f"(c[0]), "+f"(c[1]), "+f"(c[2]), "+f"(c[3])
        : "r"(a[0]), "r"(a[1]), "r"(a[2]), "r"(a[3]), "r"(b0), "r"(b1));
}
#define CP_ASYNC16(dst, src) \
    asm volatile("cp.async.cg.shared.global [%0], [%1], 16;" :: "r"(dst), "l"(src))
#define CP_COMMIT() asm volatile("cp.async.commit_group;" ::: "memory")
#define CP_WAIT_ALL() asm volatile("cp.async.wait_group 0;" ::: "memory")

// SMEM layout. Padded row stride: 72 fp16 = 144 B (conflict-free ldmatrix).
// A double-buffers are reused for h after GEMM1; B double-buffers are reused
// for We2 (chunk0 during kc=3 slot, chunk1 after GEMM1).
#define RSTRIDE 144
#define BLK 18432                   /* one [128][72] b16 image */
#define AS_OFF 0                    /* A bufs 0,1 -> later h chunks 0,1   */
#define BS_OFF (2 * BLK)            /* B bufs 0,1 -> later We2 chunks 0,1 */
#define WSUM_OFF (4 * BLK)          /* 8 warps x 64 floats = 2 KB         */
#define SMEM_BYTES (4 * BLK + 2048) /* 75776 -> 2 CTAs/SM                 */

// ---------------------------------------------------------------------------
// prep: fp16 transposed weight images. B[n][k] = W[k][n].
// ---------------------------------------------------------------------------
__global__ void prep_kernel(const float* __restrict__ We1, const float* __restrict__ We2) {
    int tid = threadIdx.x;
    if (blockIdx.x < 128) {
        int eid = blockIdx.x * 256 + tid;   // [0, 32768)
        int kc = eid >> 13;
        int n = (eid >> 6) & 127;
        int kk = eid & 63;
        float wv = We1[(2 * NODE_DIM + kc * 64 + kk) * EDGE_DIM + n];
        g_Bimg1[(size_t)kc * 8192 + n * 64 + kk] = __float2half_rn(wv);
    } else {
        int eid = (blockIdx.x - 128) * 256 + tid;  // [0, 16384)
        int kc = eid >> 13;
        int n = (eid >> 6) & 127;
        int kk = eid & 63;
        float wv = We2[(kc * 64 + kk) * EDGE_DIM + n];
        g_Bimg2[(size_t)kc * 8192 + n * 64 + kk] = __float2half_rn(wv);
    }
}

// ---------------------------------------------------------------------------
// K1: per-node projections (exact fp32). Blocks [0,512) also zero g_suma
// (stream-ordered before the fused kernel's atomic accumulation).
// ---------------------------------------------------------------------------
__global__ void proj_kernel(const float* __restrict__ na, const float* __restrict__ nb,
                            const float* __restrict__ We1, const float* __restrict__ be1) {
    __shared__ float x[NODE_DIM];
    int i = blockIdx.x, d = threadIdx.x;
    const float* src;
    float* dst;
    const float* W;
    float acc;
    if (i < N_A) {
        src = na + i * NODE_DIM;
        dst = g_aproj + i * EDGE_DIM;
        W = We1;
        acc = be1[d];
        g_suma[i * EDGE_DIM + d] = 0.f;
    } else {
        src = nb + (i - N_A) * NODE_DIM;
        dst = g_bproj + (i - N_A) * EDGE_DIM;
        W = We1 + NODE_DIM * EDGE_DIM;
        acc = 0.f;
    }
    x[d] = src[d];
    __syncthreads();
#pragma unroll 8
    for (int k = 0; k < NODE_DIM; k++) acc = fmaf(x[k], W[k * EDGE_DIM + d], acc);
    dst[d] = acc;
}

// ---------------------------------------------------------------------------
// Fused edge pipeline, single-pass fp16, pipelined, 2 CTAs/SM.
// 8 warps (4x2): warp tile 32 x 64. One 128x128 edge tile per CTA.
// Also accumulates suma partials (column sums of its tile) via atomics.
// ---------------------------------------------------------------------------
__global__ void __launch_bounds__(256, 2) fused_kernel(const float* __restrict__ edge,
                                                       const float* __restrict__ be2,
                                                       float* __restrict__ out) {
    extern __shared__ __align__(128) char smem_c[];
    const uint32_t sb = smem_u32(smem_c);
    const int tid = threadIdx.x;
    const int wid = tid >> 5;
    const int lane = tid & 31;
    const int wm = wid >> 1;
    const int wn = wid & 1;
    const int m0 = blockIdx.x * 128;
    const int a_idx = m0 >> 9;
    const int b0 = m0 & (N_B - 1);

    // ldmatrix per-lane offsets (within one [128][72] image)
    const uint32_t a_loff = (uint32_t)(wm * 32 + (lane & 15)) * RSTRIDE + ((lane >> 4) << 4);
    const uint32_t b_loff = (uint32_t)(wn * 64 + (lane & 7) + ((lane >> 4) << 3)) * RSTRIDE +
                            (((lane >> 3) & 1) << 4);

    // ---- Prologue: B chunk 0 via cp.async; A chunk 0 via LDG ----
    {
        const char* src = (const char*)g_Bimg1;  // chunk 0
#pragma unroll
        for (int i = 0; i < 4; i++) {
            int idx = tid + i * 256;            // [0, 1024) 16B units
            int n = idx >> 3;
            int p = idx & 7;
            CP_ASYNC16(sb + BS_OFF + n * RSTRIDE + p * 16, src + (size_t)idx * 16);
        }
        CP_COMMIT();
    }
    float4 regsA[8];
    {
        const float* Ag = edge + (size_t)m0 * 256;
#pragma unroll
        for (int i = 0; i < 8; i++) {
            int idx = tid + i * 256;
            int row = idx >> 4;
            int f4 = idx & 15;
            regsA[i] = *(const float4*)(Ag + (size_t)row * 256 + f4 * 4);
        }
    }

    float acc[2][8][4];
#pragma unroll
    for (int mt = 0; mt < 2; mt++)
#pragma unroll
        for (int nt = 0; nt < 8; nt++)
#pragma unroll
            for (int q = 0; q < 4; q++) acc[mt][nt][q] = 0.f;

    // ================= GEMM1: edge_tile @ We (K=256, 4 chunks) ==============
    for (int kc = 0; kc < 4; kc++) {
        const int buf = kc & 1;
        // convert + store A chunk kc (fp32 -> fp16)
#pragma unroll
        for (int i = 0; i < 8; i++) {
            int idx = tid + i * 256;
            int row = idx >> 4;
            int f4 = idx & 15;
            float4 v = regsA[i];
            __half2 h01 = __floats2half2_rn(v.x, v.y);
            __half2 h23 = __floats2half2_rn(v.z, v.w);
            *(uint2*)(smem_c + AS_OFF + buf * BLK + (uint32_t)row * RSTRIDE + f4 * 8) =
                make_uint2(*reinterpret_cast<uint32_t*>(&h01),
                           *reinterpret_cast<uint32_t*>(&h23));
        }
        CP_WAIT_ALL();     // B chunk kc landed
        __syncthreads();
        if (kc < 3) {
            // prefetch B chunk kc+1 into the other buffer (its old data consumed)
            const char* srcB = (const char*)(g_Bimg1 + (size_t)(kc + 1) * 8192);
#pragma unroll
            for (int i = 0; i < 4; i++) {
                int idx = tid + i * 256;
                int n = idx >> 3;
                int p = idx & 7;
                CP_ASYNC16(sb + BS_OFF + (buf ^ 1) * BLK + n * RSTRIDE + p * 16,
                           srcB + (size_t)idx * 16);
            }
            CP_COMMIT();
            const float* Ag = edge + (size_t)m0 * 256 + (kc + 1) * 64;
#pragma unroll
            for (int i = 0; i < 8; i++) {
                int idx = tid + i * 256;
                int row = idx >> 4;
                int f4 = idx & 15;
                regsA[i] = *(const float4*)(Ag + (size_t)row * 256 + f4 * 4);
            }
        } else {
            // kc==3: BS buf0 (chunk2) fully consumed -> prefetch We2 chunk0 there
            const char* srcW = (const char*)g_Bimg2;
#pragma unroll
            for (int i = 0; i < 4; i++) {
                int idx = tid + i * 256;
                int n = idx >> 3;
                int p = idx & 7;
                CP_ASYNC16(sb + BS_OFF + 0 * BLK + n * RSTRIDE + p * 16,
                           srcW + (size_t)idx * 16);
            }
            CP_COMMIT();
        }
        // MMA over chunk kc
#pragma unroll
        for (int ks = 0; ks < 4; ks++) {
            const uint32_t kb = ks << 5;
            const uint32_t aB = sb + AS_OFF + buf * BLK + a_loff + kb;
            const uint32_t bB = sb + BS_OFF + buf * BLK + b_loff + kb;
            uint32_t af[2][4];
            ldsm_x4(aB, af[0]);
            ldsm_x4(aB + 16 * RSTRIDE, af[1]);
#pragma unroll
            for (int np = 0; np < 4; np++) {
                uint32_t bf[4];
                ldsm_x4(bB + np * 16 * RSTRIDE, bf);
#pragma unroll
                for (int mt = 0; mt < 2; mt++) {
                    mma_f16(acc[mt][2 * np], af[mt], bf[0], bf[1]);
                    mma_f16(acc[mt][2 * np + 1], af[mt], bf[2], bf[3]);
                }
            }
        }
    }
    // All GEMM1 reads of AS/BS must retire before h / We2 overwrite them.
    __syncthreads();

    // We2 chunk1 -> BS buf1 (chunk3 consumed; sync above ordered all readers)
    {
        const char* srcW = (const char*)(g_Bimg2 + 8192);
#pragma unroll
        for (int i = 0; i < 4; i++) {
            int idx = tid + i * 256;
            int n = idx >> 3;
            int p = idx & 7;
            CP_ASYNC16(sb + BS_OFF + 1 * BLK + n * RSTRIDE + p * 16, srcW + (size_t)idx * 16);
        }
        CP_COMMIT();
    }

    // ---- Epilogue 1: h = relu(D + aproj + bproj) -> fp16 images in AS bufs ----
    {
        const int qrow = lane >> 2;
        const int qcol = (lane & 3) * 2;
#pragma unroll
        for (int mt = 0; mt < 2; mt++) {
            int r_base = wm * 32 + mt * 16 + qrow;
#pragma unroll
            for (int nt = 0; nt < 8; nt++) {
                int col = wn * 64 + nt * 8 + qcol;
                float2 ap = __ldg((const float2*)(g_aproj + a_idx * 128 + col));
#pragma unroll
                for (int hf = 0; hf < 2; hf++) {
                    int row = r_base + 8 * hf;
                    float2 bp = __ldg((const float2*)(g_bproj + (size_t)(b0 + row) * 128 + col));
                    float v0 = fmaxf(acc[mt][nt][2 * hf] + ap.x + bp.x, 0.f);
                    float v1 = fmaxf(acc[mt][nt][2 * hf + 1] + ap.y + bp.y, 0.f);
                    __half2 h01 = __floats2half2_rn(v0, v1);
                    int ch = col >> 6;
                    *(uint32_t*)(smem_c + AS_OFF + ch * BLK + (uint32_t)row * RSTRIDE +
                                 (col & 63) * 2) = *reinterpret_cast<uint32_t*>(&h01);
                    acc[mt][nt][2 * hf] = 0.f;
                    acc[mt][nt][2 * hf + 1] = 0.f;
                }
            }
        }
    }
    CP_WAIT_ALL();   // We2 chunks landed
    __syncthreads();

    // ================= GEMM2: h @ We2 (K=128, 2 chunks) =====================
#pragma unroll
    for (int ch = 0; ch < 2; ch++) {
#pragma unroll
        for (int ks = 0; ks < 4; ks++) {
            const uint32_t kb = ks << 5;
            const uint32_t aB = sb + AS_OFF + ch * BLK + a_loff + kb;
            const uint32_t bB = sb + BS_OFF + ch * BLK + b_loff + kb;
            uint32_t af[2][4];
            ldsm_x4(aB, af[0]);
            ldsm_x4(aB + 16 * RSTRIDE, af[1]);
#pragma unroll
            for (int np = 0; np < 4; np++) {
                uint32_t bf[4];
                ldsm_x4(bB + np * 16 * RSTRIDE, bf);
#pragma unroll
                for (int mt = 0; mt < 2; mt++) {
                    mma_f16(acc[mt][2 * np], af[mt], bf[0], bf[1]);
                    mma_f16(acc[mt][2 * np + 1], af[mt], bf[2], bf[3]);
                }
            }
        }
    }

    // ---- Epilogue 2: out = relu(D + be2); accumulate suma partials ----
    {
        float* wsumS = (float*)(smem_c + WSUM_OFF);  // [8 warps][64]
        const int qrow = lane >> 2;
        const int qc = lane & 3;          // qcol pair index
#pragma unroll
        for (int nt = 0; nt < 8; nt++) {
            int col = wn * 64 + nt * 8 + qc * 2;
            float2 bz = __ldg((const float2*)(be2 + col));
            float p0 = 0.f, p1 = 0.f;
#pragma unroll
            for (int mt = 0; mt < 2; mt++) {
                int r_base = wm * 32 + mt * 16 + qrow;
#pragma unroll
                for (int hf = 0; hf < 2; hf++) {
                    int row = r_base + 8 * hf;
                    float2 w;
                    w.x = fmaxf(acc[mt][nt][2 * hf] + bz.x, 0.f);
                    w.y = fmaxf(acc[mt][nt][2 * hf + 1] + bz.y, 0.f);
                    *(float2*)(out + (size_t)(m0 + row) * 128 + col) = w;
                    p0 += w.x;
                    p1 += w.y;
                }
            }
            // reduce over qrow lanes (bits 2-4); qcol bits 0-1 untouched
            p0 += __shfl_xor_sync(0xffffffffu, p0, 4);
            p0 += __shfl_xor_sync(0xffffffffu, p0, 8);
            p0 += __shfl_xor_sync(0xffffffffu, p0, 16);
            p1 += __shfl_xor_sync(0xffffffffu, p1, 4);
            p1 += __shfl_xor_sync(0xffffffffu, p1, 8);
            p1 += __shfl_xor_sync(0xffffffffu, p1, 16);
            if (lane < 4) {
                wsumS[wid * 64 + nt * 8 + lane * 2] = p0;
                wsumS[wid * 64 + nt * 8 + lane * 2 + 1] = p1;
            }
        }
        __syncthreads();
        if (tid < 128) {
            int wn2 = tid >> 6;
            int off = tid & 63;
            float s = wsumS[(0 * 2 + wn2) * 64 + off] + wsumS[(1 * 2 + wn2) * 64 + off] +
                      wsumS[(2 * 2 + wn2) * 64 + off] + wsumS[(3 * 2 + wn2) * 64 + off];
            atomicAdd(g_suma + a_idx * 128 + tid, s);
        }
    }
}

// ---------------------------------------------------------------------------
// K4: column sums only (sum over a) -> g_sumb. 512 blocks.
// ---------------------------------------------------------------------------
__global__ void __launch_bounds__(256) sum_b_kernel(const float* __restrict__ lat) {
    __shared__ float4 red[8][33];
    int b = blockIdx.x;
    int d4 = threadIdx.x & 31;
    int g = threadIdx.x >> 5;
    float x = 0.f, y = 0.f, z = 0.f, w = 0.f;
    const float4* p = (const float4*)lat + (size_t)b * 32;
    for (int a2 = g; a2 < N_A; a2 += 8) {
        float4 v = p[(size_t)a2 * (N_B * 32) + d4];
        x += v.x; y += v.y; z += v.z; w += v.w;
    }
    red[g][d4] = make_float4(x, y, z, w);
    __syncthreads();
    if (g == 0) {
#pragma unroll
        for (int k = 1; k < 8; k++) {
            float4 v = red[k][d4];
            x += v.x; y += v.y; z += v.z; w += v.w;
        }
        ((float4*)(g_sumb + b * EDGE_DIM))[d4] = make_float4(x, y, z, w);
    }
}

// ---------------------------------------------------------------------------
// K5: node MLPs
// ---------------------------------------------------------------------------
__global__ void node_mlp_kernel(const float* __restrict__ na, const float* __restrict__ nb,
                                const float* __restrict__ Wn1, const float* __restrict__ bn1,
                                const float* __restrict__ Wn2, const float* __restrict__ bn2,
                                float* __restrict__ out_nodes) {
    __shared__ float x[2 * NODE_DIM];
    __shared__ float hsm[NODE_DIM];
    int i = blockIdx.x, d = threadIdx.x;
    const float* emb;
    const float* sum;
    float* o;
    if (i < N_A) {
        emb = na + i * NODE_DIM;
        sum = g_suma + i * EDGE_DIM;
        o = out_nodes + (size_t)i * NODE_DIM;
    } else {
        emb = nb + (i - N_A) * NODE_DIM;
        sum = g_sumb + (i - N_A) * EDGE_DIM;
        o = out_nodes + (size_t)N_A * NODE_DIM + (size_t)(i - N_A) * NODE_DIM;
    }
    x[d] = emb[d];
    x[NODE_DIM + d] = sum[d];
    __syncthreads();
    float acc = bn1[d];
#pragma unroll 8
    for (int k = 0; k < 2 * NODE_DIM; k++) acc = fmaf(x[k], Wn1[k * NODE_DIM + d], acc);
    hsm[d] = fmaxf(acc, 0.f);
    __syncthreads();
    acc = bn2[d];
#pragma unroll 8
    for (int k = 0; k < NODE_DIM; k++) acc = fmaf(hsm[k], Wn2[k * NODE_DIM + d], acc);
    o[d] = fmaxf(acc, 0.f);
}

// ---------------------------------------------------------------------------
extern "C" void kernel_launch(void* const* d_in, const int* in_sizes, int n_in,
                              void* d_out, int out_size) {
    const float* edge = (const float*)d_in[0];
    const float* na   = (const float*)d_in[1];
    const float* nb   = (const float*)d_in[2];
    const float* We1  = (const float*)d_in[3];
    const float* be1  = (const float*)d_in[4];
    const float* We2  = (const float*)d_in[5];
    const float* be2  = (const float*)d_in[6];
    const float* Wn1  = (const float*)d_in[7];
    const float* bn1  = (const float*)d_in[8];
    const float* Wn2  = (const float*)d_in[9];
    const float* bn2  = (const float*)d_in[10];
    float* out = (float*)d_out;

    static int smem_set = 0;
    if (!smem_set) {
        cudaFuncSetAttribute(fused_kernel, cudaFuncAttributeMaxDynamicSharedMemorySize,
                             SMEM_BYTES);
        smem_set = 1;
    }

    prep_kernel<<<192, 256>>>(We1, We2);
    proj_kernel<<<N_A + N_B, 128>>>(na, nb, We1, be1);
    fused_kernel<<<M_EDGES / 128, 256, SMEM_BYTES>>>(edge, be2, out);
    sum_b_kernel<<<N_B, 256>>>(out);
    node_mlp_kernel<<<N_A + N_B, 128>>>(na, nb, Wn1, bn1, Wn2, bn2,
                                        out + (size_t)M_EDGES * EDGE_DIM);
}